// round 12
// baseline (speedup 1.0000x reference)
#include <cuda_runtime.h>

// Fixed problem shapes (from reference setup_inputs)
constexpr int B_    = 16;
constexpr int HS    = 640;
constexpr int WS    = 640;
constexpr int C_    = 3;
constexpr int NPIX  = 512 * 512;          // N = H_out*W_out = 262144 (2^18)
constexpr int NBITS = 18;                 // log2(NPIX)

constexpr int SMS      = 148;
constexpr int CTAS_PSM = 14;
constexpr int GRID     = SMS * 16;                    // 2368 -> uniform CTA spread
constexpr int BLOCK    = 128;
constexpr int NWARPS   = GRID * BLOCK / 32;           // 9472 warps
constexpr int NGROUPS  = (B_ * NPIX) / 32;            // 131072 groups of 32 pixels

__global__ __launch_bounds__(BLOCK, CTAS_PSM)         // 36-reg budget
void resample_nn_kernel(const float* __restrict__ idx,
                        const float* __restrict__ src,
                        float* __restrict__ out)
{
    const int lane = threadIdx.x & 31;
    const int w0   = (blockIdx.x * BLOCK + threadIdx.x) >> 5;   // global warp id

    // Per-thread constant mapping for the 3 gather/store passes:
    // pass m handles stream word w = lane + 32*m  ->  pixel p = w/3, channel = w%3
    int p_of[3], chb[3];
    #pragma unroll
    for (int m = 0; m < 3; m++) {
        const int w = lane + 32 * m;
        p_of[m] = w / 3;            // source lane holding this pixel's offset
        chb[m]  = (w % 3) * 4;      // channel byte offset
    }

    int g = w0;
    if (g >= NGROUPS) return;

    // prologue: idx for first group
    {
    }
    int   g0 = g * 32;
    int   b  = g0 >> NBITS;
    int   n0 = g0 & (NPIX - 1);
    const float* idx_b = idx + (size_t)b * 2 * NPIX;
    float r = __ldcs(idx_b + n0 + lane);
    float c = __ldcs(idx_b + NPIX + n0 + lane);

    #pragma unroll 1
    while (true) {
        // ---- compute packed offset for current group (ALU only) ----
        // trunc(x + 0.5) -> C int cast truncates toward zero, same semantics
        const int ir = (int)(r + 0.5f);
        const int ic = (int)(c + 0.5f);
        const bool valid = (ir >= 0) & (ic >= 0) & (ir < HS) & (ic < WS);
        const int irc = min(max(ir, 0), HS - 1);
        const int icc = min(max(ic, 0), WS - 1);
        // byte offset of pixel in batch tile (<2^23) | invalid flag in bit 31
        const int off    = (irc * WS + icc) * (C_ * 4);
        const int packed = valid ? off : (off | 0x80000000);

        // ---- prefetch idx of NEXT group before gathers (overlap DRAM w/ L2) ----
        const int  gn   = g + NWARPS;
        const bool more = gn < NGROUPS;          // warp-uniform
        float rn, cn;
        if (more) {
            const int g0n = gn * 32;
            const int bn  = g0n >> NBITS;
            const int n0n = g0n & (NPIX - 1);
            const float* idx_bn = idx + (size_t)bn * 2 * NPIX;
            rn = __ldcs(idx_bn + n0n + lane);
            cn = __ldcs(idx_bn + NPIX + n0n + lane);
        }

        // ---- gathers: stream word w = lane + 32m; adjacent lanes share the
        // pixel's 128B line -> L1 coalesces to ~11 wavefronts per pass ----
        const char* __restrict__ sb =
            reinterpret_cast<const char*>(src) + (size_t)b * HS * WS * C_ * sizeof(float);

        float val[3];
        #pragma unroll
        for (int m = 0; m < 3; m++) {
            const int pk = __shfl_sync(0xffffffffu, packed, p_of[m]);
            const float gv =
                __ldg(reinterpret_cast<const float*>(sb + (pk & 0x7fffffff) + chb[m]));
            val[m] = (pk >= 0) ? gv : 0.0f;
        }

        // ---- stores: same linear stream, perfectly coalesced ----
        float* ob = out + (size_t)g0 * C_;
        #pragma unroll
        for (int m = 0; m < 3; m++) {
            __stcs(ob + lane + 32 * m, val[m]);
        }

        if (!more) break;
        g  = gn;
        g0 = g * 32;
        b  = g0 >> NBITS;
        r  = rn;
        c  = cn;
    }
}

extern "C" void kernel_launch(void* const* d_in, const int* in_sizes, int n_in,
                              void* d_out, int out_size)
{
    const float* idx = (const float*)d_in[0];   // [B, 2, N] float32
    const float* src = (const float*)d_in[1];   // [B, Hs, Ws, C] float32
    float* out = (float*)d_out;                 // [B, H_out, W_out, C] float32

    resample_nn_kernel<<<GRID, BLOCK>>>(idx, src, out);
}

// round 13
// speedup vs baseline: 1.0082x; 1.0082x over previous
#include <cuda_runtime.h>

// Fixed problem shapes (from reference setup_inputs)
constexpr int B_    = 16;
constexpr int HS    = 640;
constexpr int WS    = 640;
constexpr int C_    = 3;
constexpr int NPIX  = 512 * 512;          // N = H_out*W_out = 262144 (2^18)
constexpr int NBITS = 18;                 // log2(NPIX)

constexpr int SMS      = 148;
constexpr int CTAS_PSM = 16;                          // full 64 warps/SM, 32-reg cap
constexpr int GRID     = SMS * 16;                    // 2368 -> uniform CTA spread
constexpr int BLOCK    = 128;
constexpr int NWARPS   = GRID * BLOCK / 32;           // 9472 warps
constexpr int NGROUPS  = (B_ * NPIX) / 32;            // 131072 groups of 32 pixels

__global__ __launch_bounds__(BLOCK, CTAS_PSM)
void resample_nn_kernel(const float* __restrict__ idx,
                        const float* __restrict__ src,
                        float* __restrict__ out)
{
    const int lane = threadIdx.x & 31;
    const int w0   = (blockIdx.x * BLOCK + threadIdx.x) >> 5;   // global warp id

    // Per-thread constant mapping for the 3 gather/store passes:
    // pass m handles stream word w = lane + 32*m  ->  pixel p = w/3, channel = w%3
    int p_of[3], chb[3];
    #pragma unroll
    for (int m = 0; m < 3; m++) {
        const int w = lane + 32 * m;
        p_of[m] = w / 3;            // source lane holding this pixel's offset
        chb[m]  = (w % 3) * 4;      // channel byte offset
    }

    int g = w0;
    if (g >= NGROUPS) return;

    // prologue: idx for first group
    int   g0 = g * 32;
    int   b  = g0 >> NBITS;
    int   n0 = g0 & (NPIX - 1);
    const float* idx_b = idx + (size_t)b * 2 * NPIX;
    float r = __ldcs(idx_b + n0 + lane);
    float c = __ldcs(idx_b + NPIX + n0 + lane);

    #pragma unroll 1
    while (true) {
        // ---- compute packed offset for current group (ALU only) ----
        // trunc(x + 0.5) -> C int cast truncates toward zero, same semantics
        const int ir = (int)(r + 0.5f);
        const int ic = (int)(c + 0.5f);
        const bool valid = (ir >= 0) & (ic >= 0) & (ir < HS) & (ic < WS);
        const int irc = min(max(ir, 0), HS - 1);
        const int icc = min(max(ic, 0), WS - 1);
        // byte offset of pixel in batch tile (<2^23) | invalid flag in bit 31
        const int off    = (irc * WS + icc) * (C_ * 4);
        const int packed = valid ? off : (off | 0x80000000);

        // ---- prefetch idx of NEXT group before gathers (overlap DRAM w/ L2) ----
        const int  gn   = g + NWARPS;
        const bool more = gn < NGROUPS;          // warp-uniform
        float rn, cn;
        if (more) {
            const int g0n = gn * 32;
            const int bn  = g0n >> NBITS;
            const int n0n = g0n & (NPIX - 1);
            const float* idx_bn = idx + (size_t)bn * 2 * NPIX;
            rn = __ldcs(idx_bn + n0n + lane);
            cn = __ldcs(idx_bn + NPIX + n0n + lane);
        }

        // ---- gathers: stream word w = lane + 32m; adjacent lanes share the
        // pixel's 128B line -> L1 coalesces to ~11 wavefronts per pass ----
        const char* __restrict__ sb =
            reinterpret_cast<const char*>(src) + (size_t)b * HS * WS * C_ * sizeof(float);

        float val[3];
        #pragma unroll
        for (int m = 0; m < 3; m++) {
            const int pk = __shfl_sync(0xffffffffu, packed, p_of[m]);
            const float gv =
                __ldg(reinterpret_cast<const float*>(sb + (pk & 0x7fffffff) + chb[m]));
            val[m] = (pk >= 0) ? gv : 0.0f;
        }

        // ---- stores: same linear stream, perfectly coalesced ----
        float* ob = out + (size_t)g0 * C_;
        #pragma unroll
        for (int m = 0; m < 3; m++) {
            __stcs(ob + lane + 32 * m, val[m]);
        }

        if (!more) break;
        g  = gn;
        g0 = g * 32;
        b  = g0 >> NBITS;
        r  = rn;
        c  = cn;
    }
}

extern "C" void kernel_launch(void* const* d_in, const int* in_sizes, int n_in,
                              void* d_out, int out_size)
{
    const float* idx = (const float*)d_in[0];   // [B, 2, N] float32
    const float* src = (const float*)d_in[1];   // [B, Hs, Ws, C] float32
    float* out = (float*)d_out;                 // [B, H_out, W_out, C] float32

    resample_nn_kernel<<<GRID, BLOCK>>>(idx, src, out);
}

// round 14
// speedup vs baseline: 1.0713x; 1.0626x over previous
#include <cuda_runtime.h>

// Fixed problem shapes (from reference setup_inputs)
constexpr int B_    = 16;
constexpr int HS    = 640;
constexpr int WS    = 640;
constexpr int C_    = 3;
constexpr int NPIX  = 512 * 512;          // N = H_out*W_out = 262144 (2^18)
constexpr int NBITS = 18;                 // log2(NPIX)

constexpr int SMS      = 148;
constexpr int CTAS_PSM = 16;
constexpr int GRID     = SMS * CTAS_PSM;              // 2368 -> 16 CTAs on every SM
constexpr int BLOCK    = 128;                         // 64 warps/SM uniform
constexpr int NWARPS   = GRID * BLOCK / 32;           // 9472 warps
constexpr int NGROUPS  = (B_ * NPIX) / 32;            // 131072 groups of 32 pixels

__global__ __launch_bounds__(BLOCK, CTAS_PSM)
void resample_nn_kernel(const float* __restrict__ idx,
                        const float* __restrict__ src,
                        float* __restrict__ out)
{
    const int lane = threadIdx.x & 31;
    const int w0   = (blockIdx.x * BLOCK + threadIdx.x) >> 5;   // global warp id

    // Per-thread constant mapping for the 3 gather/store passes:
    // pass m handles stream word w = lane + 32*m  ->  pixel p = w/3, channel = w%3
    int p_of[3], chb[3];
    #pragma unroll
    for (int m = 0; m < 3; m++) {
        const int w = lane + 32 * m;
        p_of[m] = w / 3;            // source lane holding this pixel's offset
        chb[m]  = (w % 3) * 4;      // channel byte offset
    }

    #pragma unroll 1
    for (int g = w0; g < NGROUPS; g += NWARPS) {
        const int g0 = g * 32;                    // first pixel (global, b*N + n)
        const int b  = g0 >> NBITS;
        const int n0 = g0 & (NPIX - 1);           // multiple of 32, no wrap for +lane

        // idx layout: [B, 2, N] -> rows at b*2N + n, cols at b*2N + N + n
        const float* idx_b = idx + (size_t)b * 2 * NPIX;
        const float r = __ldcs(idx_b + n0 + lane);
        const float c = __ldcs(idx_b + NPIX + n0 + lane);

        // Register-free L2 prefetch of NEXT iteration's idx lines (one 128B
        // line each for r and c; lane 0 only). Hides idx DRAM latency without
        // extending any register scoreboard chain.
        const int gn = g + NWARPS;
        if (lane == 0 && gn < NGROUPS) {
            const int g0n = gn * 32;
            const int bn  = g0n >> NBITS;
            const int n0n = g0n & (NPIX - 1);
            const float* idx_bn = idx + (size_t)bn * 2 * NPIX;
            asm volatile("prefetch.global.L2 [%0];" :: "l"(idx_bn + n0n));
            asm volatile("prefetch.global.L2 [%0];" :: "l"(idx_bn + NPIX + n0n));
        }

        // trunc(x + 0.5) -> C int cast truncates toward zero, same semantics
        const int ir = (int)(r + 0.5f);
        const int ic = (int)(c + 0.5f);
        const bool valid = (ir >= 0) & (ic >= 0) & (ir < HS) & (ic < WS);
        const int irc = min(max(ir, 0), HS - 1);
        const int icc = min(max(ic, 0), WS - 1);

        // packed: byte offset of pixel in batch tile (<2^23) | invalid flag in bit 31
        const int off    = (irc * WS + icc) * (C_ * 4);
        const int packed = valid ? off : (off | 0x80000000);

        const char* __restrict__ sb =
            reinterpret_cast<const char*>(src) + (size_t)b * HS * WS * C_ * sizeof(float);

        // 3 passes: gather stream word w = lane + 32m; adjacent lanes share the
        // pixel's 128B line -> L1 coalesces to ~11 wavefronts per pass.
        float val[3];
        #pragma unroll
        for (int m = 0; m < 3; m++) {
            const int pk = __shfl_sync(0xffffffffu, packed, p_of[m]);
            const float gv =
                __ldg(reinterpret_cast<const float*>(sb + (pk & 0x7fffffff) + chb[m]));
            val[m] = (pk >= 0) ? gv : 0.0f;
        }

        // out layout: [B, N, C]; group covers words [3*g0, 3*g0+96) — the same
        // linear stream we gathered. Perfectly coalesced streaming stores.
        float* ob = out + (size_t)g0 * C_;
        #pragma unroll
        for (int m = 0; m < 3; m++) {
            __stcs(ob + lane + 32 * m, val[m]);
        }
    }
}

extern "C" void kernel_launch(void* const* d_in, const int* in_sizes, int n_in,
                              void* d_out, int out_size)
{
    const float* idx = (const float*)d_in[0];   // [B, 2, N] float32
    const float* src = (const float*)d_in[1];   // [B, Hs, Ws, C] float32
    float* out = (float*)d_out;                 // [B, H_out, W_out, C] float32

    resample_nn_kernel<<<GRID, BLOCK>>>(idx, src, out);
}